// round 11
// baseline (speedup 1.0000x reference)
#include <cuda_runtime.h>
#include <cstdint>

#define Bn 16
#define IMG (512*512)           // 2^18
#define NPX (Bn*IMG)            // 4194304
#define RS 128                  // region size
#define RPI 16                  // 4x4 regions per image
#define NREG (Bn*RPI)           // 256
#define THREADS 1024
#define NSUB 32                 // 8x4 subtiles of 16x32
#define ST 131                  // smem row stride (gcd(131,32)=1)
#define MS_WORDS (130*ST)
#define KS_WORDS (128*ST)
#define SMEM_BYTES ((MS_WORDS + KS_WORDS)*4)   // ~135 KB
#define MAX_BLOCK_ITERS 2048
#define QCAP 1024
#define ALLBITS 0x1FF
#define GUARD_ITERS 2000000

// ---- device globals (static scratch) ----
__device__ float g_bufA[NPX];          // xh
__device__ float g_bufB[NPX];          // rec2 -> Rmax
__device__ float g_bufC[NPX];          // M -> R
__device__ int      q_items[QCAP];     // region id + 1; 0 = empty slot
__device__ unsigned q_head, q_tail;
__device__ int      q_state[NREG];     // 0 idle, 1 queued, 2 running, 3 running-dirty
__device__ int      q_wake[NREG];      // directional wake bits
__device__ int      q_pending;
__device__ unsigned g_cc[Bn];
__device__ int g_hasone, g_haszero;
__device__ unsigned g_bar_count = 0;
__device__ volatile unsigned g_bar_gen = 0;

// ---- software grid barrier (all blocks resident: 1 block/SM via smem) ----
__device__ __forceinline__ void grid_sync(int nb) {
    __syncthreads();
    if (threadIdx.x == 0) {
        __threadfence();
        unsigned gen = g_bar_gen;
        unsigned t = atomicAdd(&g_bar_count, 1u);
        if (t == (unsigned)nb - 1u) {
            atomicExch(&g_bar_count, 0u);
            __threadfence();
            g_bar_gen = gen + 1u;
        } else {
            while (g_bar_gen == gen) { __nanosleep(32); }
        }
        __threadfence();
    }
    __syncthreads();
}

__device__ __forceinline__ float f3max(float a, float b, float c) {
    return fmaxf(fmaxf(a, b), c);
}

// ---- queue ops (single-thread callers) ----
__device__ void q_push(int r, int bits) {
    if (bits) atomicOr(&q_wake[r], bits);
    for (int tries = 0; tries < 64; tries++) {
        int s = atomicCAS(&q_state[r], 0, 1);
        if (s == 0) {                       // we enqueue
            atomicAdd(&q_pending, 1);
            unsigned t = atomicAdd(&q_tail, 1u);
            q_items[t % QCAP] = r + 1;
            __threadfence();
            return;
        }
        if (s == 2) {                        // running: mark dirty
            if (atomicCAS(&q_state[r], 2, 3) == 2) return;
            continue;                        // state moved; retry
        }
        return;                              // 1 or 3: already pending
    }
}

// returns region id, -1 = no work right now, -2 = all done
__device__ int q_pop() {
    unsigned h = ((volatile unsigned*)&q_head)[0];
    unsigned t = ((volatile unsigned*)&q_tail)[0];
    if (h == t) {
        __threadfence();
        if (((volatile int*)&q_pending)[0] == 0) return -2;
        return -1;
    }
    if (atomicCAS(&q_head, h, h + 1u) != h) return -1;   // lost race
    int v = 0;
    for (int sp = 0; sp < (1 << 22); sp++) {             // wait for slot fill
        v = ((volatile int*)q_items)[h % QCAP];
        if (v) break;
    }
    q_items[h % QCAP] = 0;
    __threadfence();
    return v - 1;
}

__device__ void q_finish(int r, int changed, int capped, int b, int ry, int rx) {
    if (capped) atomicOr(&q_wake[r], ALLBITS);
    if (changed) {
        #pragma unroll
        for (int dy = -1; dy <= 1; dy++)
            #pragma unroll
            for (int dx = -1; dx <= 1; dx++) {
                if (dy == 0 && dx == 0) continue;
                int ny = ry + dy, nx = rx + dx;
                if ((unsigned)ny < 4u && (unsigned)nx < 4u) {
                    int bit = 1 << ((1 - dy) * 3 + (1 - dx));  // dir: target->source
                    q_push((b << 4) + (ny << 2) + nx, bit);
                }
            }
    }
    int s = atomicCAS(&q_state[r], 2, 0);
    if (s == 3) {                            // re-dirtied while running
        atomicExch(&q_state[r], 1);
        atomicAdd(&q_pending, 1);
        unsigned t = atomicAdd(&q_tail, 1u);
        q_items[t % QCAP] = r + 1;
        __threadfence();
    } else if (capped) {
        q_push(r, 0);
    }
    __threadfence();
    atomicSub(&q_pending, 1);
}

// ---- one 4-directional sweep of a 16x32 subtile (R10 verbatim) ----
__device__ int relax_once(float* MS, const float* KS, int wy, int wx, int lane) {
    int ch = 0;
    const unsigned F = 0xffffffffu;
    const int r0 = (wy << 4) + 1;
    const int c0 = (wx << 5) + 1;

    float haloL = 0.0f, haloR = 0.0f;
    if (lane < 18) {
        haloL = MS[(r0 - 1 + lane) * ST + (c0 - 1)];
        haloR = MS[(r0 - 1 + lane) * ST + (c0 + 32)];
    }
    float haloTR = MS[(r0 - 1) * ST + (c0 - 1 + lane)];
    float haloTL = MS[(r0 - 1) * ST + (c0 + 1 + lane)];
    float haloBR = MS[(r0 + 16) * ST + (c0 - 1 + lane)];
    float haloBL = MS[(r0 + 16) * ST + (c0 + 1 + lane)];

    // DOWN
    {
        const int c = c0 + lane;
        float pc = MS[(r0 - 1) * ST + c];
        #pragma unroll 4
        for (int yy = 0; yy < 16; yy++) {
            float l  = __shfl_up_sync(F, pc, 1);
            float r  = __shfl_down_sync(F, pc, 1);
            float hl = __shfl_sync(F, haloL, yy);
            float hr = __shfl_sync(F, haloR, yy);
            if (lane == 0)  l = hl;
            if (lane == 31) r = hr;
            const int row = r0 + yy;
            float cur = MS[row * ST + c];
            float nv  = fminf(fmaxf(cur, f3max(l, pc, r)), KS[(row - 1) * ST + (c - 1)]);
            if (nv > cur) { MS[row * ST + c] = nv; ch = 1; }
            pc = nv;
        }
    }
    // UP
    {
        const int c = c0 + lane;
        float pc = MS[(r0 + 16) * ST + c];
        #pragma unroll 4
        for (int yy = 15; yy >= 0; yy--) {
            float l  = __shfl_up_sync(F, pc, 1);
            float r  = __shfl_down_sync(F, pc, 1);
            float hl = __shfl_sync(F, haloL, yy + 2);
            float hr = __shfl_sync(F, haloR, yy + 2);
            if (lane == 0)  l = hl;
            if (lane == 31) r = hr;
            const int row = r0 + yy;
            float cur = MS[row * ST + c];
            float nv  = fminf(fmaxf(cur, f3max(l, pc, r)), KS[(row - 1) * ST + (c - 1)]);
            if (nv > cur) { MS[row * ST + c] = nv; ch = 1; }
            pc = nv;
        }
    }
    // RIGHT
    {
        const int lr   = lane & 15;
        const int row  = r0 + lr;
        const bool act = (lane < 16);
        float pc = MS[row * ST + (c0 - 1)];
        #pragma unroll 4
        for (int xx = 0; xx < 32; xx++) {
            float u  = __shfl_up_sync(F, pc, 1);
            float d  = __shfl_down_sync(F, pc, 1);
            float ht = __shfl_sync(F, haloTR, xx);
            float hb = __shfl_sync(F, haloBR, xx);
            if (lr == 0)  u = ht;
            if (lr == 15) d = hb;
            const int c = c0 + xx;
            float cur = MS[row * ST + c];
            float nv  = fminf(fmaxf(cur, f3max(u, pc, d)), KS[(row - 1) * ST + (c - 1)]);
            if (act && nv > cur) { MS[row * ST + c] = nv; ch = 1; }
            pc = nv;
        }
    }
    // LEFT
    {
        const int lr   = lane & 15;
        const int row  = r0 + lr;
        const bool act = (lane < 16);
        float pc = MS[row * ST + (c0 + 32)];
        #pragma unroll 4
        for (int xx = 31; xx >= 0; xx--) {
            float u  = __shfl_up_sync(F, pc, 1);
            float d  = __shfl_down_sync(F, pc, 1);
            float ht = __shfl_sync(F, haloTL, xx);
            float hb = __shfl_sync(F, haloBL, xx);
            if (lr == 0)  u = ht;
            if (lr == 15) d = hb;
            const int c = c0 + xx;
            float cur = MS[row * ST + c];
            float nv  = fminf(fmaxf(cur, f3max(u, pc, d)), KS[(row - 1) * ST + (c - 1)]);
            if (act && nv > cur) { MS[row * ST + c] = nv; ch = 1; }
            pc = nv;
        }
    }
    return ch;
}

// ---- reconstruct(m, mask): async work-queue dataflow ----
__device__ void reconstruct(float* m, const float* mask, int nb,
                            float* MS, float* KS) {
    const int tid  = threadIdx.x;
    const int wid  = tid >> 5;
    const int lane = tid & 31;
    const int wy   = wid >> 2, wx = wid & 3;
    __shared__ int s_sub[2][NSUB];
    __shared__ int s_r, s_wake, s_regch;
    const float NEGINF = __int_as_float(0xff800000);

    for (int guard = 0; guard < GUARD_ITERS; guard++) {
        __syncthreads();                       // protects s_r rewrite + smem reuse
        if (tid == 0) s_r = q_pop();
        __syncthreads();
        const int r = s_r;
        if (r == -2) break;
        if (r == -1) { __nanosleep(100); continue; }

        if (tid == 0) {
            atomicCAS(&q_state[r], 1, 2);      // claim: queued -> running
            s_wake  = atomicExch(&q_wake[r], 0);
            s_regch = 0;
        }
        __syncthreads();
        const int wake = s_wake;
        const int b  = r >> 4, idx = r & 15;
        const int ry = idx >> 2, rx = idx & 3;
        const size_t base = ((size_t)b) << 18;
        const int gy0 = ry * RS, gx0 = rx * RS;

        // load marker region + 1-px halo (out-of-image -> -inf)
        for (int i = tid; i < 130 * 130; i += THREADS) {
            int yy = i / 130, xx = i - yy * 130;
            int gy = gy0 + yy - 1, gx = gx0 + xx - 1;
            float v = NEGINF;
            if ((unsigned)gy < 512u && (unsigned)gx < 512u)
                v = __ldcg(m + base + ((size_t)gy << 9) + gx);
            MS[yy * ST + xx] = v;
        }
        // load mask (interior)
        for (int i = tid; i < 128 * 128; i += THREADS) {
            int yy = i >> 7, xx = i & 127;
            KS[yy * ST + xx] = __ldcg(mask + base + ((size_t)(gy0 + yy) << 9) + (gx0 + xx));
        }
        __syncthreads();

        // initial dirty set from directional wake bits (bit 4 = all dirty)
        int dirty0 = (wake & (1 << 4)) ? 1 : 0;
        if (!dirty0) {
            #pragma unroll
            for (int k = 0; k < 9; k++) {
                if (k == 4 || !(wake & (1 << k))) continue;
                int dy = k / 3 - 1, dx = k % 3 - 1;
                int ty = (dy < 0) ? (wy == 0) : (dy > 0) ? (wy == 7) : 1;
                int tx = (dx < 0) ? (wx == 0) : (dx > 0) ? (wx == 3) : 1;
                if (ty && tx) dirty0 = 1;
            }
        }

        // block-level fixpoint: warps relax subtiles, halos via smem
        int capped = 1;
        for (int it = 0; it < MAX_BLOCK_ITERS; it++) {
            const int p = it & 1, q = 1 - p;
            int dirty;
            if (it == 0) dirty = dirty0;
            else {
                dirty = 0;
                #pragma unroll
                for (int dy = -1; dy <= 1; dy++)
                    #pragma unroll
                    for (int dx = -1; dx <= 1; dx++) {
                        int ny = wy + dy, nx = wx + dx;
                        if ((unsigned)ny < 8u && (unsigned)nx < 4u)
                            dirty |= s_sub[q][(ny << 2) + nx];
                    }
            }
            int ch = 0;
            if (dirty) ch = relax_once(MS, KS, wy, wx, lane);
            ch = __any_sync(0xffffffffu, ch);
            if (lane == 0) { s_sub[p][wid] = ch; if (ch) s_regch = 1; }
            __syncthreads();
            int any = 0;
            #pragma unroll
            for (int w = 0; w < NSUB; w++) any |= s_sub[p][w];
            if (!any) { capped = 0; break; }
        }

        const int changed = s_regch;
        if (changed) {
            for (int i = tid; i < 128 * 128; i += THREADS) {
                int yy = i >> 7, xx = i & 127;
                __stcg(m + base + ((size_t)(gy0 + yy) << 9) + (gx0 + xx),
                       MS[(yy + 1) * ST + (xx + 1)]);
            }
        }
        __syncthreads();                       // writeback complete block-wide
        if (tid == 0) {
            __threadfence();                   // publish before pushes
            q_finish(r, changed, capped, b, ry, rx);
        }
    }
    grid_sync(nb);
}

// queue reset + seed (call from all threads, follow with grid_sync)
__device__ void q_reset(int gtid, int nt) {
    for (int i = gtid; i < QCAP; i += nt) q_items[i] = (i < NREG) ? (i + 1) : 0;
    for (int i = gtid; i < NREG; i += nt) { q_state[i] = 1; q_wake[i] = ALLBITS; }
    if (gtid == 0) { q_head = 0u; q_tail = (unsigned)NREG; q_pending = NREG; }
}

__global__ void __launch_bounds__(THREADS, 1)
mega(const float* __restrict__ x, const float* __restrict__ hh,
     const float* __restrict__ u, float* __restrict__ out,
     int nb, long long xh_off, int write_cc)
{
    extern __shared__ float dynsm[];
    float* MS = dynsm;
    float* KS = dynsm + MS_WORDS;
    const int lane = threadIdx.x & 31;
    const int gtid = blockIdx.x * THREADS + threadIdx.x;
    const int nt   = nb * THREADS;

    // reset state; marker = x - h[b]  (coalesced streams)
    q_reset(gtid, nt);
    if (gtid < Bn) g_cc[gtid] = 0u;
    if (gtid == 0) { g_hasone = 0; g_haszero = 0; }
    for (int i = gtid; i < NPX; i += nt) {
        float hv = __ldg(hh + (i >> 18));
        __stcg(g_bufA + i, x[i] - hv);
    }
    grid_sync(nb);

    // xh = reconstruct(x - h, x)
    reconstruct(g_bufA, x, nb, MS, KS);

    // write xh to output; marker2 = xh - eps; reseed queue
    for (int i = gtid; i < NPX; i += nt) {
        float v = __ldcg(g_bufA + i);
        out[xh_off + i] = v;
        __stcg(g_bufB + i, v - 1e-5f);
    }
    q_reset(gtid, nt);
    grid_sync(nb);
    // rec2 = reconstruct(xh - eps, xh)
    reconstruct(g_bufB, g_bufA, nb, MS, KS);

    // Rmax = (xh - rec2 > 0); M = min(u, Rmax); has-one/has-zero; reseed
    int one = 0, zero = 0;
    for (int i = gtid; i < NPX; i += nt) {
        float rec = __ldcg(g_bufB + i);
        float xh  = __ldcg(g_bufA + i);
        float rmx = ((xh - rec) > 0.0f) ? 1.0f : 0.0f;
        if (rmx != 0.0f) one = 1; else zero = 1;
        __stcg(g_bufB + i, rmx);
        __stcg(g_bufC + i, fminf(u[i], rmx));
    }
    if (__any_sync(0xffffffffu, one)  && lane == 0) atomicOr(&g_hasone, 1);
    if (__any_sync(0xffffffffu, zero) && lane == 0) atomicOr(&g_haszero, 1);
    q_reset(gtid, nt);
    grid_sync(nb);
    // R = reconstruct(M, Rmax)
    reconstruct(g_bufC, g_bufB, nb, MS, KS);

    // Detection = (u == R); CC[b] via ballot+popc (exact integer counts)
    __shared__ unsigned s_cnt[Bn];
    if (threadIdx.x < Bn) s_cnt[threadIdx.x] = 0u;
    __syncthreads();
    for (int i = gtid; i < NPX; i += nt) {
        unsigned mball = __ballot_sync(0xffffffffu, u[i] == __ldcg(g_bufC + i));
        if (lane == 0 && mball) atomicAdd(&s_cnt[i >> 18], (unsigned)__popc(mball));
    }
    __syncthreads();
    if (threadIdx.x < Bn && s_cnt[threadIdx.x])
        atomicAdd(&g_cc[threadIdx.x], s_cnt[threadIdx.x]);
    grid_sync(nb);

    if (write_cc && blockIdx.x == 0 && threadIdx.x < Bn) {
        int ho = ((volatile int*)&g_hasone)[0];
        int hz = ((volatile int*)&g_haszero)[0];
        float d  = (ho && hz) ? 1.0f : 0.0f;   // max(Rmax) - min(Rmax)
        float cc = (float)((volatile unsigned*)g_cc)[threadIdx.x];
        out[threadIdx.x] = fminf(cc, 100.0f * d * cc);
    }
}

extern "C" void kernel_launch(void* const* d_in, const int* in_sizes, int n_in,
                              void* d_out, int out_size) {
    const float* x = (const float*)d_in[0];
    const float* h = (const float*)d_in[1];
    const float* u = (const float*)d_in[2];
    float* out = (float*)d_out;

    int dev = 0;
    cudaGetDevice(&dev);
    int sms = 0;
    cudaDeviceGetAttribute(&sms, cudaDevAttrMultiProcessorCount, dev);
    if (sms <= 0) sms = 148;

    cudaFuncSetAttribute(mega, cudaFuncAttributeMaxDynamicSharedMemorySize, SMEM_BYTES);
    int occ = 0;
    cudaOccupancyMaxActiveBlocksPerMultiprocessor(&occ, mega, THREADS, SMEM_BYTES);
    if (occ < 1) occ = 1;
    int nb = sms * occ;   // all blocks resident -> software grid barrier safe

    long long xh_off = (long long)out_size - NPX;   // [CC_(16) | xh(N)]
    int write_cc = (xh_off >= Bn) ? 1 : 0;
    if (xh_off < 0) xh_off = 0;

    mega<<<nb, THREADS, SMEM_BYTES>>>(x, h, u, out, nb, xh_off, write_cc);
}